// round 14
// baseline (speedup 1.0000x reference)
#include <cuda_runtime.h>
#include <cuda_bf16.h>
#include <math.h>
#include <stdint.h>

#define B_ 256
#define T_ 128
#define D_ 256
#define H_ 512
#define BT_ (B_*T_)
#define G4H_ 2048
#define XHAT_OFF (T_*B_*2)   /* outs [T,B,2] first, then xhats [T,B,D] */
#define NCTA_GROUP 64        /* loop: 4 independent groups of 64 CTAs */
#define LDF 72               /* bf16 frag-tile row stride (pre-GEMMs) */
#define LKC 68               /* loop A-chunk row stride: 64 + 4 pad */
#define LWK 516              /* loop W row stride: 512 + 4 pad */

// ---- device scratch (allocation-free rule) ----
__device__ float g_gammaH[(size_t)T_*B_*H_];      // [T,B,H]
__device__ float g_preGates[(size_t)T_*B_*G4H_];  // [T,B,4H]
__device__ float g_hbuf[2][B_][H_];               // double-buffered h
__device__ float g_wT[(D_+H_)*D_];                // wgxT [256,256] then wghT [512,256]
__device__ float g_W1T[10*H_];                    // W1 transposed [10][512]
__device__ unsigned g_barC[4][32];                // per-group barrier counter
__device__ unsigned g_barS[4][32];                // per-group barrier flag

typedef unsigned long long u64;
union F2U { u64 u; float2 f; };

__device__ __forceinline__ u64 ffma2(u64 a, u64 b, u64 c) {
    u64 d; asm("fma.rn.f32x2 %0,%1,%2,%3;" : "=l"(d) : "l"(a), "l"(b), "l"(c)); return d;
}
__device__ __forceinline__ float sigm(float x){ return 1.f/(1.f+expf(-x)); }
__device__ __forceinline__ float ldcg(const float* p){
    float v; asm volatile("ld.global.cg.f32 %0,[%1];" : "=f"(v) : "l"(p)); return v;
}
__device__ __forceinline__ float4 ldcg4(const float* p){
    float4 v; asm volatile("ld.global.cg.v4.f32 {%0,%1,%2,%3},[%4];"
        : "=f"(v.x),"=f"(v.y),"=f"(v.z),"=f"(v.w) : "l"(p)); return v;
}
__device__ __forceinline__ void stcg(float* p, float v){
    asm volatile("st.global.cg.f32 [%0],%1;" :: "l"(p), "f"(v));
}
__device__ __forceinline__ uint32_t s2u(const void* p){
    uint32_t a;
    asm("{ .reg .u64 t; cvta.to.shared.u64 t, %1; cvt.u32.u64 %0, t; }" : "=r"(a) : "l"(p));
    return a;
}

// ============================================================================
// HMMA bf16x3 machinery (pre-GEMMs only — R10 proven)
// ============================================================================
__device__ __forceinline__ void ldm4(uint32_t* r, uint32_t addr){
    asm volatile("ldmatrix.sync.aligned.m8n8.x4.shared.b16 {%0,%1,%2,%3}, [%4];"
        : "=r"(r[0]),"=r"(r[1]),"=r"(r[2]),"=r"(r[3]) : "r"(addr));
}
__device__ __forceinline__ void mma_bf16(float* d, const uint32_t* a,
                                         uint32_t b0, uint32_t b1){
    asm volatile("mma.sync.aligned.m16n8k16.row.col.f32.bf16.bf16.f32 "
        "{%0,%1,%2,%3}, {%4,%5,%6,%7}, {%8,%9}, {%0,%1,%2,%3};"
        : "+f"(d[0]), "+f"(d[1]), "+f"(d[2]), "+f"(d[3])
        : "r"(a[0]), "r"(a[1]), "r"(a[2]), "r"(a[3]), "r"(b0), "r"(b1));
}
__device__ __forceinline__ void split4(float4 v, uint2& hi, uint2& lo){
    __nv_bfloat162 h01 = __floats2bfloat162_rn(v.x, v.y);
    __nv_bfloat162 h23 = __floats2bfloat162_rn(v.z, v.w);
    __nv_bfloat162 l01 = __floats2bfloat162_rn(v.x - __bfloat162float(h01.x),
                                               v.y - __bfloat162float(h01.y));
    __nv_bfloat162 l23 = __floats2bfloat162_rn(v.z - __bfloat162float(h23.x),
                                               v.w - __bfloat162float(h23.y));
    hi = make_uint2(*(uint32_t*)&h01, *(uint32_t*)&h23);
    lo = make_uint2(*(uint32_t*)&l01, *(uint32_t*)&l23);
}

// Pre-GEMM core: acc[2][8][4] += A[128 @arow0][256] @ B[128 @brow0][256]^T
__device__ __forceinline__ void hmma_gemm(
    __nv_bfloat16* sm, const float* __restrict__ A, int arow0, int lda,
    const float* __restrict__ Bsrc, int brow0, int ldb, float acc[2][8][4])
{
    __nv_bfloat16 *sAhi = sm, *sAlo = sm + 128*LDF;
    __nv_bfloat16 *sBhi = sm + 2*128*LDF, *sBlo = sm + 3*128*LDF;
    const int tid = threadIdx.x, lane = tid & 31, wid = tid >> 5;
    const int wm = wid & 3, wn = wid >> 2;
    const int g = lane >> 3, r8 = lane & 7;

    for (int ch = 0; ch < 4; ch++) {
        const int k0 = ch*64;
        if (ch) __syncthreads();
        #pragma unroll 4
        for (int i = tid; i < 2048; i += 256) {
            int rr = i >> 4, q = (i & 15) << 2;
            uint2 hi, lo;
            split4(*(const float4*)&A[(size_t)(arow0+rr)*lda + k0 + q], hi, lo);
            *(uint2*)&sAhi[rr*LDF + q] = hi;
            *(uint2*)&sAlo[rr*LDF + q] = lo;
        }
        #pragma unroll 4
        for (int i = tid; i < 2048; i += 256) {
            int rr = i >> 4, q = (i & 15) << 2;
            uint2 hi, lo;
            split4(*(const float4*)&Bsrc[(size_t)(brow0+rr)*ldb + k0 + q], hi, lo);
            *(uint2*)&sBhi[rr*LDF + q] = hi;
            *(uint2*)&sBlo[rr*LDF + q] = lo;
        }
        __syncthreads();
        #pragma unroll
        for (int ks = 0; ks < 4; ks++) {
            const int kk = ks*16;
            uint32_t ahi[2][4], alo[2][4], bhi[4][4], blo[4][4];
            #pragma unroll
            for (int mi = 0; mi < 2; mi++) {
                int m = wm*32 + mi*16 + (g & 1)*8 + r8;
                int k = kk + (g >> 1)*8;
                ldm4(ahi[mi], s2u(&sAhi[m*LDF + k]));
                ldm4(alo[mi], s2u(&sAlo[m*LDF + k]));
            }
            #pragma unroll
            for (int np = 0; np < 4; np++) {
                int n = wn*64 + np*16 + (g >> 1)*8 + r8;
                int k = kk + (g & 1)*8;
                ldm4(bhi[np], s2u(&sBhi[n*LDF + k]));
                ldm4(blo[np], s2u(&sBlo[n*LDF + k]));
            }
            #pragma unroll
            for (int mi = 0; mi < 2; mi++)
                #pragma unroll
                for (int nj = 0; nj < 8; nj++) {
                    uint32_t h0 = bhi[nj>>1][(nj&1)*2], h1 = bhi[nj>>1][(nj&1)*2+1];
                    uint32_t l0 = blo[nj>>1][(nj&1)*2], l1 = blo[nj>>1][(nj&1)*2+1];
                    mma_bf16(acc[mi][nj], ahi[mi], h0, h1);
                    mma_bf16(acc[mi][nj], ahi[mi], l0, l1);
                    mma_bf16(acc[mi][nj], alo[mi], h0, h1);
                }
        }
    }
}
#define HM_SMEM (4*128*LDF*2)

// ---------------------------------------------------------------------------
// G12 (HMMA): gamma_x (+imputation->xhat) and gamma_h.  grid (BT/128, 6).
// ---------------------------------------------------------------------------
__global__ void __launch_bounds__(256,2) k_g12_h(
    const float* __restrict__ dt,  const float* __restrict__ hgx,
    const float* __restrict__ hgh, const float* __restrict__ x,
    const float* __restrict__ mask, const float* __restrict__ xmean,
    float* __restrict__ out)
{
    extern __shared__ __nv_bfloat16 smb[];
    float acc[2][8][4] = {};
    const int m0 = blockIdx.x*128, n0 = blockIdx.y*128;
    hmma_gemm(smb, dt, m0, D_, (const float*)g_wT, n0, D_, acc);

    const int lane = threadIdx.x & 31, wid = threadIdx.x >> 5;
    const int wm = wid & 3, wn = wid >> 2;
    const int tg = lane >> 2, tc = (lane & 3)*2;

    #pragma unroll
    for (int mi = 0; mi < 2; mi++) {
        #pragma unroll
        for (int nj = 0; nj < 8; nj++) {
            const float* a4 = acc[mi][nj];
            int ng = n0 + wn*64 + nj*8 + tc;
            #pragma unroll
            for (int h = 0; h < 2; h++) {
                int row = m0 + wm*32 + mi*16 + tg + h*8;   // = b*T + t
                int b = row >> 7, t = row & (T_-1);
                float v0 = a4[h*2], v1 = a4[h*2+1];
                if (blockIdx.y < 2) {
                    int d = ng;
                    float o[2];
                    #pragma unroll
                    for (int e = 0; e < 2; e++) {
                        float v = e ? v1 : v0; int dd = d + e;
                        float gm = expf(-fmaxf(v + hgx[dd], 0.f));
                        float mv = mask[(size_t)row*D_ + dd];
                        float xt = x[(size_t)row*D_ + dd];
                        float xm = xmean[dd];
                        float imp = (t == 0) ? xm
                                  : fmaf(gm, x[(size_t)(row-1)*D_ + dd], (1.f-gm)*xm);
                        o[e] = xt*mv + (1.f-mv)*imp;
                    }
                    *(float2*)&out[XHAT_OFF + ((size_t)t*B_ + b)*D_ + d] = make_float2(o[0], o[1]);
                } else {
                    int u = ng - 256;
                    float2 o;
                    o.x = expf(-fmaxf(v0 + hgh[u],   0.f));
                    o.y = expf(-fmaxf(v1 + hgh[u+1], 0.f));
                    *(float2*)&g_gammaH[((size_t)t*B_ + b)*H_ + u] = o;
                }
            }
        }
    }
}

// ---------------------------------------------------------------------------
// G3 (HMMA): pre_gates = xs @ W_ih^T + b_ih + b_hh.  grid (BT/128, 16).
// ---------------------------------------------------------------------------
__global__ void __launch_bounds__(256,2) k_g3_h(
    const float* __restrict__ xsrc, const float* __restrict__ Wih,
    const float* __restrict__ bih,  const float* __restrict__ bhh)
{
    extern __shared__ __nv_bfloat16 smb[];
    float acc[2][8][4] = {};
    const int m0 = blockIdx.x*128, n0 = blockIdx.y*128;
    hmma_gemm(smb, xsrc, m0, D_, Wih, n0, D_, acc);

    const int lane = threadIdx.x & 31, wid = threadIdx.x >> 5;
    const int wm = wid & 3, wn = wid >> 2;
    const int tg = lane >> 2, tc = (lane & 3)*2;

    #pragma unroll
    for (int mi = 0; mi < 2; mi++) {
        #pragma unroll
        for (int nj = 0; nj < 8; nj++) {
            const float* a4 = acc[mi][nj];
            int n = n0 + wn*64 + nj*8 + tc;
            float bi0 = bih[n] + bhh[n], bi1 = bih[n+1] + bhh[n+1];
            #pragma unroll
            for (int h = 0; h < 2; h++) {
                int row = m0 + wm*32 + mi*16 + tg + h*8;   // = t*B + b
                *(float2*)&g_preGates[(size_t)row*G4H_ + n] =
                    make_float2(a4[h*2] + bi0, a4[h*2+1] + bi1);
            }
        }
    }
}

// ============================================================================
// misc small kernels
// ============================================================================
__global__ void __launch_bounds__(H_) k_init(const float* __restrict__ h0)
{
    g_hbuf[0][blockIdx.x][threadIdx.x] = h0[threadIdx.x];
}

__global__ void __launch_bounds__(256) k_tr(const float* __restrict__ wgx,
                                            const float* __restrict__ wgh,
                                            const float* __restrict__ W1)
{
    int blk = blockIdx.x, k = threadIdx.x;
    if (blk < 256) g_wT[blk*D_ + k] = wgx[k*D_ + blk];
    else if (blk < 768) { int n = blk - 256; g_wT[D_*D_ + n*D_ + k] = wgh[k*H_ + n]; }
    else {
        int z = blk - 768;
        g_W1T[z*H_ + k]       = W1[k*10 + z];
        g_W1T[z*H_ + k + 256] = W1[(k+256)*10 + z];
    }
}

// per-group grid barrier (64 CTAs). 128 passes/launch -> even -> replay-safe.
__device__ __forceinline__ void gridbar(int grp, unsigned &sense)
{
    __syncthreads();
    if (threadIdx.x == 0) {
        unsigned s = sense ^ 1, old;
        asm volatile("atom.acq_rel.gpu.global.add.u32 %0,[%1],1;"
                     : "=r"(old) : "l"(&g_barC[grp][0]));
        if (old == NCTA_GROUP-1) {
            asm volatile("st.relaxed.gpu.global.u32 [%0],%1;" :: "l"(&g_barC[grp][0]), "r"(0u));
            asm volatile("st.release.gpu.global.u32 [%0],%1;" :: "l"(&g_barS[grp][0]), "r"(s));
        } else {
            unsigned v;
            do {
                asm volatile("ld.acquire.gpu.global.u32 %0,[%1];" : "=r"(v) : "l"(&g_barS[grp][0]));
            } while (v != s);
        }
    }
    __syncthreads();
    sense ^= 1;
}

// ============================================================================
// Persistent recurrent loop — fp32 exact, full-K, fused cell, ONE barrier/step.
// 256 CTAs in 4 independent mb-groups of 64.  cta = mb*64 + ug:
//   b-tile [mb*64, +64), c-columns { gate*512 + ug*8 + ul : gate<4, ul<8 }.
// W slice [32 rows = gate*8+ul][512 k] resident in smem for all steps.
// A = gamma_h ⊙ h staged in 8 chunks of 64k, double-buffered w/ LDG prefetch.
// Epilogue: acc + preGates -> full i,f,g,o per thread -> cell inline -> h.
// Thread (tx=tid&7 -> u = u0+tx; ty=tid>>3 -> b = b0+ty+32i, i<2). acc[2][4].
// ============================================================================
__global__ void __launch_bounds__(256,2) k_loop(
    const float* __restrict__ Whh, const float* __restrict__ c0,
    const float* __restrict__ tp,  const float* __restrict__ wt,
    const float* __restrict__ ht,  const float* __restrict__ b1,
    const float* __restrict__ W2,  const float* __restrict__ b2,
    float* __restrict__ out)
{
    extern __shared__ float sm[];
    float *Wsm = sm;                      // [32][LWK]
    float *ahs = sm + 32*LWK;             // [2][64][LKC]
    float *h1s = ahs + 2*64*LKC;          // 512
    float *zs  = h1s + 512;               // 16

    const int tid = threadIdx.x, cta = blockIdx.x;
    const int mb = cta >> 6, ug = cta & 63;
    const int grp = mb;
    const int b0 = mb*64, u0 = ug*8;
    const int bc = b0 + ug;               // head batch (in-group)
    const int tx = tid & 7, ty = tid >> 3;
    const int u  = u0 + tx;
    unsigned sense = 0;

    // resident W: Wsm[g*8+ul][k] = Whh[g*512 + u0 + ul][k], k<512
    for (int i = tid; i < 32*128; i += 256) {
        int r = i >> 7, q = (i & 127) << 2;
        int g = r >> 3, ul = r & 7;
        *(float4*)&Wsm[r*LWK + q] =
            *(const float4*)&Whh[(size_t)(g*512 + u0 + ul)*H_ + q];
    }

    float c_reg[2];
    c_reg[0] = c0[u]; c_reg[1] = c0[u];   // c0 is [1,H] broadcast
    const float wtr = wt[u], htr = ht[u];
    __syncthreads();

    for (int t = 0; t < T_; t++) {
        const int p = t & 1;              // read hbuf[p], write hbuf[p^1]

        // ---- h1s for head(t-1) + stage chunk 0 ----
        if (t > 0)
            for (int i = tid; i < 512; i += 256)
                h1s[i] = ldcg(&g_hbuf[p][bc][i]);
        {
            #pragma unroll
            for (int l = 0; l < 4; l++) {
                int i = tid + l*256;
                int r = i >> 4, q = (i & 15) << 2;
                float4 g = *(const float4*)&g_gammaH[((size_t)t*B_ + b0 + r)*H_ + q];
                float4 h = ldcg4(&g_hbuf[p][b0 + r][q]);
                g.x *= h.x; g.y *= h.y; g.z *= h.z; g.w *= h.w;
                *(float4*)&ahs[r*LKC + q] = g;
            }
        }
        __syncthreads();

        // ---- output head for step t-1 (batch bc) ----
        if (t > 0) {
            int wid = tid >> 5, lane = tid & 31;
            for (int z = wid; z < 10; z += 8) {
                float s = 0.f;
                const float* wv = g_W1T + z*H_;
                #pragma unroll 4
                for (int k = lane; k < H_; k += 32) s = fmaf(h1s[k], __ldg(&wv[k]), s);
                #pragma unroll
                for (int off = 16; off; off >>= 1) s += __shfl_xor_sync(0xffffffffu, s, off);
                if (lane == 0) zs[z] = sigm(s + b1[z]);
            }
            __syncthreads();
            if (tid == 0) {
                float z0 = b2[0], z1 = b2[1];
                #pragma unroll
                for (int j = 0; j < 10; j++) {
                    z0 = fmaf(zs[j], W2[j*2 + 0], z0);
                    z1 = fmaf(zs[j], W2[j*2 + 1], z1);
                }
                z0 = sigm(z0); z1 = sigm(z1);
                float m = fmaxf(z0, z1);
                float e0 = expf(z0 - m), e1 = expf(z1 - m);
                float inv = 1.f/(e0 + e1);
                out[((size_t)(t-1)*B_ + bc)*2 + 0] = e0*inv;
                out[((size_t)(t-1)*B_ + bc)*2 + 1] = e1*inv;
            }
        }

        // ---- full-K GEMM: 8 chunks of 64k, double-buffered ----
        u64 acc[2][4] = {};
        #pragma unroll 1
        for (int ch = 0; ch < 8; ch++) {
            const int buf = ch & 1;
            float4 gP[4], hP[4];
            if (ch < 7) {                 // prefetch chunk ch+1
                const int kc = (ch+1)*64;
                #pragma unroll
                for (int l = 0; l < 4; l++) {
                    int i = tid + l*256;
                    int r = i >> 4, q = (i & 15) << 2;
                    gP[l] = *(const float4*)&g_gammaH[((size_t)t*B_ + b0 + r)*H_ + kc + q];
                    hP[l] = ldcg4(&g_hbuf[p][b0 + r][kc + q]);
                }
            }
            // compute chunk ch from ahs[buf]
            const float* Ab = ahs + buf*64*LKC;
            const float* Wb = Wsm + ch*64;
            #pragma unroll 2
            for (int k4 = 0; k4 < 16; k4++) {
                float4 a0 = *(const float4*)&Ab[ty*LKC + 4*k4];
                float4 a1 = *(const float4*)&Ab[(ty+32)*LKC + 4*k4];
                #pragma unroll
                for (int g = 0; g < 4; g++) {
                    float4 w = *(const float4*)&Wb[(g*8+tx)*LWK + 4*k4];
                    u64 wlo = ((const u64*)&w)[0], whi = ((const u64*)&w)[1];
                    acc[0][g] = ffma2(((const u64*)&a0)[0], wlo, acc[0][g]);
                    acc[0][g] = ffma2(((const u64*)&a0)[1], whi, acc[0][g]);
                    acc[1][g] = ffma2(((const u64*)&a1)[0], wlo, acc[1][g]);
                    acc[1][g] = ffma2(((const u64*)&a1)[1], whi, acc[1][g]);
                }
            }
            if (ch < 7) {                 // store prefetched chunk into other buf
                float* Dn = ahs + (buf^1)*64*LKC;
                #pragma unroll
                for (int l = 0; l < 4; l++) {
                    int i = tid + l*256;
                    int r = i >> 4, q = (i & 15) << 2;
                    float4 g = gP[l], h = hP[l];
                    g.x *= h.x; g.y *= h.y; g.z *= h.z; g.w *= h.w;
                    *(float4*)&Dn[r*LKC + q] = g;
                }
                __syncthreads();
            }
        }

        // ---- fused cell epilogue: thread owns (b, u) pairs ----
        #pragma unroll
        for (int i = 0; i < 2; i++) {
            const int b = b0 + ty + 32*i;
            const float* pre = &g_preGates[((size_t)t*B_ + b)*G4H_];
            F2U v;
            v.u = acc[i][0]; float gi = v.f.x + v.f.y + pre[u];
            v.u = acc[i][1]; float gf = v.f.x + v.f.y + pre[512 + u];
            v.u = acc[i][2]; float gg = v.f.x + v.f.y + pre[1024 + u];
            v.u = acc[i][3]; float go = v.f.x + v.f.y + pre[1536 + u];
            float gh  = g_gammaH[((size_t)t*B_ + b)*H_ + u];
            float tpv = tp[b*T_ + t];
            float c1 = sigm(gf)*(gh*c_reg[i]) + sigm(gi)*tanhf(gg);
            float h1 = sigm(go)*tanhf(c1);
            float gtv = sigm(tpv*wtr + htr);
            c_reg[i] = gtv*c1;
            stcg(&g_hbuf[p^1][b][u], gtv*h1);
        }
        gridbar(grp, sense);
    }

    // ---- final head: step 127, h in hbuf[0], batch bc ----
    for (int i = tid; i < 512; i += 256)
        h1s[i] = ldcg(&g_hbuf[0][bc][i]);
    __syncthreads();
    {
        int wid = tid >> 5, lane = tid & 31;
        for (int z = wid; z < 10; z += 8) {
            float s = 0.f;
            const float* wv = g_W1T + z*H_;
            #pragma unroll 4
            for (int k = lane; k < H_; k += 32) s = fmaf(h1s[k], __ldg(&wv[k]), s);
            #pragma unroll
            for (int off = 16; off; off >>= 1) s += __shfl_xor_sync(0xffffffffu, s, off);
            if (lane == 0) zs[z] = sigm(s + b1[z]);
        }
        __syncthreads();
        if (tid == 0) {
            float z0 = b2[0], z1 = b2[1];
            #pragma unroll
            for (int j = 0; j < 10; j++) {
                z0 = fmaf(zs[j], W2[j*2 + 0], z0);
                z1 = fmaf(zs[j], W2[j*2 + 1], z1);
            }
            z0 = sigm(z0); z1 = sigm(z1);
            float m = fmaxf(z0, z1);
            float e0 = expf(z0 - m), e1 = expf(z1 - m);
            float inv = 1.f/(e0 + e1);
            out[((size_t)127*B_ + bc)*2 + 0] = e0*inv;
            out[((size_t)127*B_ + bc)*2 + 1] = e1*inv;
        }
    }
}

// ---------------------------------------------------------------------------
extern "C" void kernel_launch(void* const* d_in, const int* in_sizes, int n_in,
                              void* d_out, int out_size)
{
    const float* x     = (const float*)d_in[0];
    const float* dt    = (const float*)d_in[1];
    const float* mask  = (const float*)d_in[2];
    const float* tp    = (const float*)d_in[3];
    const float* xmean = (const float*)d_in[4];
    const float* h0    = (const float*)d_in[5];
    const float* c0    = (const float*)d_in[6];
    const float* wgx   = (const float*)d_in[7];
    const float* hgx   = (const float*)d_in[8];
    const float* wgh   = (const float*)d_in[9];
    const float* hgh   = (const float*)d_in[10];
    const float* wt    = (const float*)d_in[11];
    const float* ht    = (const float*)d_in[12];
    const float* Wih   = (const float*)d_in[13];
    const float* Whh   = (const float*)d_in[14];
    const float* bih   = (const float*)d_in[15];
    const float* bhh   = (const float*)d_in[16];
    const float* W1    = (const float*)d_in[17];
    const float* b1    = (const float*)d_in[18];
    const float* W2    = (const float*)d_in[19];
    const float* b2    = (const float*)d_in[20];
    float* out = (float*)d_out;

    const int LOOP_SMEM = (32*LWK + 2*64*LKC + 512 + 16) * 4;   // 102,976 B
    static bool attr_done = false;
    if (!attr_done) {
        cudaFuncSetAttribute(k_g12_h, cudaFuncAttributeMaxDynamicSharedMemorySize, HM_SMEM);
        cudaFuncSetAttribute(k_g3_h,  cudaFuncAttributeMaxDynamicSharedMemorySize, HM_SMEM);
        cudaFuncSetAttribute(k_loop,  cudaFuncAttributeMaxDynamicSharedMemorySize, LOOP_SMEM);
        attr_done = true;
    }

    k_init<<<B_, H_>>>(h0);
    k_tr<<<778, 256>>>(wgx, wgh, W1);
    k_g12_h<<<dim3(BT_/128, 6),  256, HM_SMEM>>>(dt, hgx, hgh, x, mask, xmean, out);
    k_g3_h<<<dim3(BT_/128, 16), 256, HM_SMEM>>>(out + XHAT_OFF, Wih, bih, bhh);
    k_loop<<<256, 256, LOOP_SMEM>>>(Whh, c0, tp, wt, ht, b1, W2, b2, out);
}

// round 15
// speedup vs baseline: 1.2669x; 1.2669x over previous
#include <cuda_runtime.h>
#include <cuda_bf16.h>
#include <math.h>
#include <stdint.h>

#define B_ 256
#define T_ 128
#define D_ 256
#define H_ 512
#define BT_ (B_*T_)
#define G4H_ 2048
#define XHAT_OFF (T_*B_*2)   /* outs [T,B,2] first, then xhats [T,B,D] */
#define LDK 132              /* loop smem row: Kc=128 + 4 pad */
#define NCTA_GROUP 64        /* loop: 4 independent groups of 64 CTAs */
#define LDF 72               /* bf16 frag-tile row stride: 144B, 16B-aligned, cf */

// ---- device scratch (allocation-free rule) ----
__device__ float g_gammaH[(size_t)T_*B_*H_];      // [T,B,H]
__device__ float g_preGates[(size_t)T_*B_*G4H_];  // [T,B,4H]
__device__ float g_part[4][B_][G4H_];             // split-K partials
__device__ float g_hbuf[2][B_][H_];               // double-buffered h
__device__ float g_W1T[10*H_];                    // W1 transposed [10][512]
// pre-split bf16 operands (hi/lo)
__device__ __nv_bfloat16 g_dtHi[(size_t)BT_*D_],  g_dtLo[(size_t)BT_*D_];
__device__ __nv_bfloat16 g_xsHi[(size_t)BT_*D_],  g_xsLo[(size_t)BT_*D_];
__device__ __nv_bfloat16 g_WihHi[G4H_*D_],        g_WihLo[G4H_*D_];
__device__ __nv_bfloat16 g_wTHi[(D_+H_)*D_],      g_wTLo[(D_+H_)*D_];
__device__ unsigned g_barC[4][32];
__device__ unsigned g_barS[4][32];

typedef unsigned long long u64;
union F2U { u64 u; float2 f; };

__device__ __forceinline__ u64 ffma2(u64 a, u64 b, u64 c) {
    u64 d; asm("fma.rn.f32x2 %0,%1,%2,%3;" : "=l"(d) : "l"(a), "l"(b), "l"(c)); return d;
}
__device__ __forceinline__ float sigm(float x){ return 1.f/(1.f+expf(-x)); }
__device__ __forceinline__ float ldcg(const float* p){
    float v; asm volatile("ld.global.cg.f32 %0,[%1];" : "=f"(v) : "l"(p)); return v;
}
__device__ __forceinline__ float2 ldcg2(const float* p){
    float2 v; asm volatile("ld.global.cg.v2.f32 {%0,%1},[%2];"
        : "=f"(v.x),"=f"(v.y) : "l"(p)); return v;
}
__device__ __forceinline__ float4 ldcg4(const float* p){
    float4 v; asm volatile("ld.global.cg.v4.f32 {%0,%1,%2,%3},[%4];"
        : "=f"(v.x),"=f"(v.y),"=f"(v.z),"=f"(v.w) : "l"(p)); return v;
}
__device__ __forceinline__ void stcg(float* p, float v){
    asm volatile("st.global.cg.f32 [%0],%1;" :: "l"(p), "f"(v));
}
__device__ __forceinline__ void stcg2(float* p, float2 v){
    asm volatile("st.global.cg.v2.f32 [%0],{%1,%2};" :: "l"(p), "f"(v.x), "f"(v.y));
}
__device__ __forceinline__ uint32_t s2u(const void* p){
    uint32_t a;
    asm("{ .reg .u64 t; cvta.to.shared.u64 t, %1; cvt.u32.u64 %0, t; }" : "=r"(a) : "l"(p));
    return a;
}

// ============================================================================
// HMMA bf16x3 machinery (mma.sync m16n8k16 — baseline PTX)
// ============================================================================
__device__ __forceinline__ void ldm4(uint32_t* r, uint32_t addr){
    asm volatile("ldmatrix.sync.aligned.m8n8.x4.shared.b16 {%0,%1,%2,%3}, [%4];"
        : "=r"(r[0]),"=r"(r[1]),"=r"(r[2]),"=r"(r[3]) : "r"(addr));
}
__device__ __forceinline__ void mma_bf16(float* d, const uint32_t* a,
                                         uint32_t b0, uint32_t b1){
    asm volatile("mma.sync.aligned.m16n8k16.row.col.f32.bf16.bf16.f32 "
        "{%0,%1,%2,%3}, {%4,%5,%6,%7}, {%8,%9}, {%0,%1,%2,%3};"
        : "+f"(d[0]), "+f"(d[1]), "+f"(d[2]), "+f"(d[3])
        : "r"(a[0]), "r"(a[1]), "r"(a[2]), "r"(a[3]), "r"(b0), "r"(b1));
}
__device__ __forceinline__ void split4(float4 v, uint2& hi, uint2& lo){
    __nv_bfloat162 h01 = __floats2bfloat162_rn(v.x, v.y);
    __nv_bfloat162 h23 = __floats2bfloat162_rn(v.z, v.w);
    __nv_bfloat162 l01 = __floats2bfloat162_rn(v.x - __bfloat162float(h01.x),
                                               v.y - __bfloat162float(h01.y));
    __nv_bfloat162 l23 = __floats2bfloat162_rn(v.z - __bfloat162float(h23.x),
                                               v.w - __bfloat162float(h23.y));
    hi = make_uint2(*(uint32_t*)&h01, *(uint32_t*)&h23);
    lo = make_uint2(*(uint32_t*)&l01, *(uint32_t*)&l23);
}

// Pre-GEMM core: acc[2][8][4] += A[128 @arow0] @ B[128 @brow0]^T, K=256.
// A/B are PRE-SPLIT bf16 hi/lo, row-major ld=256. Staging = pure uint4 copy.
__device__ __forceinline__ void hmma_gemm_bf(
    __nv_bfloat16* sm,
    const __nv_bfloat16* __restrict__ Ahi, const __nv_bfloat16* __restrict__ Alo, int arow0,
    const __nv_bfloat16* __restrict__ Bhi, const __nv_bfloat16* __restrict__ Blo, int brow0,
    float acc[2][8][4])
{
    __nv_bfloat16 *sAhi = sm, *sAlo = sm + 128*LDF;
    __nv_bfloat16 *sBhi = sm + 2*128*LDF, *sBlo = sm + 3*128*LDF;
    const int tid = threadIdx.x, lane = tid & 31, wid = tid >> 5;
    const int wm = wid & 3, wn = wid >> 2;
    const int g = lane >> 3, r8 = lane & 7;

    for (int ch = 0; ch < 4; ch++) {
        const int k0 = ch*64;
        if (ch) __syncthreads();
        #pragma unroll 4
        for (int i = tid; i < 1024; i += 256) {
            int r = i >> 3, u = (i & 7) << 3;       // 8 bf16 per uint4
            size_t ga = (size_t)(arow0+r)*D_ + k0 + u;
            size_t gb = (size_t)(brow0+r)*D_ + k0 + u;
            *(uint4*)&sAhi[r*LDF + u] = *(const uint4*)&Ahi[ga];
            *(uint4*)&sAlo[r*LDF + u] = *(const uint4*)&Alo[ga];
            *(uint4*)&sBhi[r*LDF + u] = *(const uint4*)&Bhi[gb];
            *(uint4*)&sBlo[r*LDF + u] = *(const uint4*)&Blo[gb];
        }
        __syncthreads();
        #pragma unroll
        for (int ks = 0; ks < 4; ks++) {
            const int kk = ks*16;
            uint32_t ahi[2][4], alo[2][4], bhi[4][4], blo[4][4];
            #pragma unroll
            for (int mi = 0; mi < 2; mi++) {
                int m = wm*32 + mi*16 + (g & 1)*8 + r8;
                int k = kk + (g >> 1)*8;
                ldm4(ahi[mi], s2u(&sAhi[m*LDF + k]));
                ldm4(alo[mi], s2u(&sAlo[m*LDF + k]));
            }
            #pragma unroll
            for (int np = 0; np < 4; np++) {
                int n = wn*64 + np*16 + (g >> 1)*8 + r8;
                int k = kk + (g & 1)*8;
                ldm4(bhi[np], s2u(&sBhi[n*LDF + k]));
                ldm4(blo[np], s2u(&sBlo[n*LDF + k]));
            }
            #pragma unroll
            for (int mi = 0; mi < 2; mi++)
                #pragma unroll
                for (int nj = 0; nj < 8; nj++) {
                    uint32_t h0 = bhi[nj>>1][(nj&1)*2], h1 = bhi[nj>>1][(nj&1)*2+1];
                    uint32_t l0 = blo[nj>>1][(nj&1)*2], l1 = blo[nj>>1][(nj&1)*2+1];
                    mma_bf16(acc[mi][nj], ahi[mi], h0, h1);
                    mma_bf16(acc[mi][nj], ahi[mi], l0, l1);
                    mma_bf16(acc[mi][nj], alo[mi], h0, h1);
                }
        }
    }
}
#define HM_SMEM (4*128*LDF*2)

// ---------------------------------------------------------------------------
// conversions: dt + Wih -> bf16 hi/lo.  grid 8704 x 256, 4 elem/thread.
// ---------------------------------------------------------------------------
__global__ void __launch_bounds__(256) k_cvt(const float* __restrict__ dt,
                                             const float* __restrict__ Wih)
{
    size_t idx = (size_t)blockIdx.x*1024 + threadIdx.x*4;
    uint2 hi, lo;
    if (idx < (size_t)BT_*D_) {
        split4(*(const float4*)&dt[idx], hi, lo);
        *(uint2*)&g_dtHi[idx] = hi;
        *(uint2*)&g_dtLo[idx] = lo;
    } else {
        size_t j = idx - (size_t)BT_*D_;
        split4(*(const float4*)&Wih[j], hi, lo);
        *(uint2*)&g_WihHi[j] = hi;
        *(uint2*)&g_WihLo[j] = lo;
    }
}

// transposes: wgx/wgh -> g_wTHi/Lo bf16 [N][K]; W1 -> g_W1T fp32
__global__ void __launch_bounds__(256) k_tr(const float* __restrict__ wgx,
                                            const float* __restrict__ wgh,
                                            const float* __restrict__ W1)
{
    int blk = blockIdx.x, k = threadIdx.x;
    if (blk < 768) {
        float v = (blk < 256) ? wgx[k*D_ + blk] : wgh[k*H_ + (blk-256)];
        __nv_bfloat16 h = __float2bfloat16_rn(v);
        __nv_bfloat16 l = __float2bfloat16_rn(v - __bfloat162float(h));
        g_wTHi[blk*D_ + k] = h;
        g_wTLo[blk*D_ + k] = l;
    } else {
        int z = blk - 768;
        g_W1T[z*H_ + k]       = W1[k*10 + z];
        g_W1T[z*H_ + k + 256] = W1[(k+256)*10 + z];
    }
}

__global__ void __launch_bounds__(H_) k_init(const float* __restrict__ h0)
{
    g_hbuf[0][blockIdx.x][threadIdx.x] = h0[threadIdx.x];
}

// ---------------------------------------------------------------------------
// G12 (HMMA): gamma_x (+imputation->xhat, + xs bf16 split) and gamma_h.
// grid (BT/128, 6):  by<2 gamma_x cols, by>=2 gamma_h cols.
// ---------------------------------------------------------------------------
__global__ void __launch_bounds__(256,2) k_g12_h(
    const float* __restrict__ hgx, const float* __restrict__ hgh,
    const float* __restrict__ x,   const float* __restrict__ mask,
    const float* __restrict__ xmean, float* __restrict__ out)
{
    extern __shared__ __nv_bfloat16 smb[];
    float acc[2][8][4] = {};
    const int m0 = blockIdx.x*128, n0 = blockIdx.y*128;
    hmma_gemm_bf(smb, g_dtHi, g_dtLo, m0, g_wTHi, g_wTLo, n0, acc);

    const int lane = threadIdx.x & 31, wid = threadIdx.x >> 5;
    const int wm = wid & 3, wn = wid >> 2;
    const int tg = lane >> 2, tc = (lane & 3)*2;

    #pragma unroll
    for (int mi = 0; mi < 2; mi++) {
        #pragma unroll
        for (int nj = 0; nj < 8; nj++) {
            const float* a4 = acc[mi][nj];
            int ng = n0 + wn*64 + nj*8 + tc;
            #pragma unroll
            for (int h = 0; h < 2; h++) {
                int row = m0 + wm*32 + mi*16 + tg + h*8;   // = b*T + t
                int b = row >> 7, t = row & (T_-1);
                float v0 = a4[h*2], v1 = a4[h*2+1];
                if (blockIdx.y < 2) {
                    int d = ng;
                    float o[2];
                    #pragma unroll
                    for (int e = 0; e < 2; e++) {
                        float v = e ? v1 : v0; int dd = d + e;
                        float gm = expf(-fmaxf(v + hgx[dd], 0.f));
                        float mv = mask[(size_t)row*D_ + dd];
                        float xt = x[(size_t)row*D_ + dd];
                        float xm = xmean[dd];
                        float imp = (t == 0) ? xm
                                  : fmaf(gm, x[(size_t)(row-1)*D_ + dd], (1.f-gm)*xm);
                        o[e] = xt*mv + (1.f-mv)*imp;
                    }
                    size_t oidx = ((size_t)t*B_ + b)*D_ + d;
                    *(float2*)&out[XHAT_OFF + oidx] = make_float2(o[0], o[1]);
                    __nv_bfloat162 xh = __floats2bfloat162_rn(o[0], o[1]);
                    __nv_bfloat162 xl = __floats2bfloat162_rn(
                        o[0] - __bfloat162float(xh.x), o[1] - __bfloat162float(xh.y));
                    *(uint32_t*)&g_xsHi[oidx] = *(uint32_t*)&xh;
                    *(uint32_t*)&g_xsLo[oidx] = *(uint32_t*)&xl;
                } else {
                    int u = ng - 256;
                    float2 o;
                    o.x = expf(-fmaxf(v0 + hgh[u],   0.f));
                    o.y = expf(-fmaxf(v1 + hgh[u+1], 0.f));
                    *(float2*)&g_gammaH[((size_t)t*B_ + b)*H_ + u] = o;
                }
            }
        }
    }
}

// ---------------------------------------------------------------------------
// G3 (HMMA): pre_gates = xs @ W_ih^T + b_ih + b_hh.  grid (BT/128, 16).
// ---------------------------------------------------------------------------
__global__ void __launch_bounds__(256,2) k_g3_h(
    const float* __restrict__ bih, const float* __restrict__ bhh)
{
    extern __shared__ __nv_bfloat16 smb[];
    float acc[2][8][4] = {};
    const int m0 = blockIdx.x*128, n0 = blockIdx.y*128;
    hmma_gemm_bf(smb, g_xsHi, g_xsLo, m0, g_WihHi, g_WihLo, n0, acc);

    const int lane = threadIdx.x & 31, wid = threadIdx.x >> 5;
    const int wm = wid & 3, wn = wid >> 2;
    const int tg = lane >> 2, tc = (lane & 3)*2;

    #pragma unroll
    for (int mi = 0; mi < 2; mi++) {
        #pragma unroll
        for (int nj = 0; nj < 8; nj++) {
            const float* a4 = acc[mi][nj];
            int n = n0 + wn*64 + nj*8 + tc;
            float bi0 = bih[n] + bhh[n], bi1 = bih[n+1] + bhh[n+1];
            #pragma unroll
            for (int h = 0; h < 2; h++) {
                int row = m0 + wm*32 + mi*16 + tg + h*8;   // = t*B + b
                *(float2*)&g_preGates[(size_t)row*G4H_ + n] =
                    make_float2(a4[h*2] + bi0, a4[h*2+1] + bi1);
            }
        }
    }
}

// ============================================================================
// per-group grid barrier (64 CTAs). 256 passes/launch -> replay-safe.
// ============================================================================
__device__ __forceinline__ void gridbar(int grp, unsigned &sense)
{
    __syncthreads();
    if (threadIdx.x == 0) {
        unsigned s = sense ^ 1, old;
        asm volatile("atom.acq_rel.gpu.global.add.u32 %0,[%1],1;"
                     : "=r"(old) : "l"(&g_barC[grp][0]));
        if (old == NCTA_GROUP-1) {
            asm volatile("st.relaxed.gpu.global.u32 [%0],%1;" :: "l"(&g_barC[grp][0]), "r"(0u));
            asm volatile("st.release.gpu.global.u32 [%0],%1;" :: "l"(&g_barS[grp][0]), "r"(s));
        } else {
            unsigned v;
            do {
                asm volatile("ld.acquire.gpu.global.u32 %0,[%1];" : "=r"(v) : "l"(&g_barS[grp][0]));
            } while (v != s);
        }
    }
    __syncthreads();
    sense ^= 1;
}

// ============================================================================
// Persistent recurrent loop (fp32 FFMA2 — exact; R10 structure verbatim).
// 256 CTAs in 4 independent (half,mb) groups of 64.  CTA = (half,mb,nb,kb):
//   tile b[b0,+64) x c[c0i,+128) x k[k0,+128), split-K 4.
// Cell: float2-vectorized, u2 = 2*tid (+512 strides), batch bc.
// ============================================================================
__device__ __forceinline__ void mm64(const float* __restrict__ As,
                                     const float* __restrict__ Bs,
                                     u64 acc[4][8], int tx, int ty)
{
    #pragma unroll 1
    for (int k4 = 0; k4 < 32; k4++) {
        float4 a4[4], w4[8];
        #pragma unroll
        for (int i = 0; i < 4; i++) a4[i] = *(const float4*)&As[(ty+16*i)*LDK + 4*k4];
        #pragma unroll
        for (int j = 0; j < 8; j++) w4[j] = *(const float4*)&Bs[(tx+16*j)*LDK + 4*k4];
        #pragma unroll
        for (int i = 0; i < 4; i++) {
            u64 alo = ((const u64*)&a4[i])[0], ahi = ((const u64*)&a4[i])[1];
            #pragma unroll
            for (int j = 0; j < 8; j++) {
                acc[i][j] = ffma2(alo, ((const u64*)&w4[j])[0], acc[i][j]);
                acc[i][j] = ffma2(ahi, ((const u64*)&w4[j])[1], acc[i][j]);
            }
        }
    }
}

__device__ __forceinline__ void load_tile(float* dst, const float* src,
                                          int rows, int row0, int ld, int col0)
{
    for (int i = threadIdx.x; i < rows*32; i += 256) {
        int r = i >> 5, q = (i & 31) << 2;
        *(float4*)&dst[r*LDK + q] = *(const float4*)&src[(size_t)(row0+r)*ld + col0 + q];
    }
}

__global__ void __launch_bounds__(256,2) k_loop(
    const float* __restrict__ Whh, const float* __restrict__ c0,
    const float* __restrict__ tp,  const float* __restrict__ wt,
    const float* __restrict__ ht,  const float* __restrict__ b1,
    const float* __restrict__ W2,  const float* __restrict__ b2,
    float* __restrict__ out)
{
    extern __shared__ float sm[];
    float *Wsm = sm;
    float *ahs = sm + 128*LDK;
    float *h1s = sm + 192*LDK;
    float *zs  = h1s + 512;
    float *tps = zs + 16;

    const int tid = threadIdx.x;
    const int half  = blockIdx.x >> 7;
    const int local = blockIdx.x & 127;
    const int grp   = blockIdx.x >> 6;           // (half, mb) group, 0..3
    const int kb = local & 3, nb = (local >> 2) & 15, mb = local >> 6;
    const int b0 = half*128 + mb*64, c0i = nb*128, k0 = kb*128;
    const int bc = half*128 + local;
    const int tx = tid & 15, ty = tid >> 4;
    const int u2 = tid*2;
    unsigned sense = 0;

    load_tile(Wsm, Whh, 128, c0i, H_, k0);
    for (int i = tid; i < 128; i += 256) tps[i] = tp[bc*T_ + i];

    float2 c_reg = *(const float2*)&c0[u2];
    float2 wtr   = *(const float2*)&wt[u2];
    float2 htr   = *(const float2*)&ht[u2];
    __syncthreads();

    for (int t = 0; t < T_; t++) {
        const int p = t & 1;

        if (t > 0)
            for (int i = tid; i < 512; i += 256)
                h1s[i] = ldcg(&g_hbuf[p][bc][i]);
        for (int i = tid; i < 64*32; i += 256) {
            int r = i >> 5, q = (i & 31) << 2;
            int bg = b0 + r;
            float4 g = *(const float4*)&g_gammaH[((size_t)t*B_ + bg)*H_ + k0 + q];
            float4 h = ldcg4(&g_hbuf[p][bg][k0 + q]);
            g.x *= h.x; g.y *= h.y; g.z *= h.z; g.w *= h.w;
            *(float4*)&ahs[r*LDK + q] = g;
        }
        __syncthreads();

        if (t > 0) {
            int wid = tid >> 5, lane = tid & 31;
            for (int z = wid; z < 10; z += 8) {
                float s = 0.f;
                const float* wv = g_W1T + z*H_;
                #pragma unroll 4
                for (int k = lane; k < H_; k += 32) s = fmaf(h1s[k], __ldg(&wv[k]), s);
                #pragma unroll
                for (int off = 16; off; off >>= 1) s += __shfl_xor_sync(0xffffffffu, s, off);
                if (lane == 0) zs[z] = sigm(s + b1[z]);
            }
            __syncthreads();
            if (tid == 0) {
                float z0 = b2[0], z1 = b2[1];
                #pragma unroll
                for (int j = 0; j < 10; j++) {
                    z0 = fmaf(zs[j], W2[j*2 + 0], z0);
                    z1 = fmaf(zs[j], W2[j*2 + 1], z1);
                }
                z0 = sigm(z0); z1 = sigm(z1);
                float m = fmaxf(z0, z1);
                float e0 = expf(z0 - m), e1 = expf(z1 - m);
                float inv = 1.f/(e0 + e1);
                out[((size_t)(t-1)*B_ + bc)*2 + 0] = e0*inv;
                out[((size_t)(t-1)*B_ + bc)*2 + 1] = e1*inv;
            }
        }

        u64 acc[4][8] = {};
        mm64(ahs, Wsm, acc, tx, ty);
        #pragma unroll
        for (int i = 0; i < 4; i++) {
            int bg = b0 + ty + 16*i;
            #pragma unroll
            for (int j = 0; j < 8; j++) {
                F2U v; v.u = acc[i][j];
                stcg(&g_part[kb][bg][c0i + tx + 16*j], v.f.x + v.f.y);
            }
        }
        gridbar(grp, sense);

        // ---- cell (register c-state, float2 vectorized), batch bc ----
        {
            const float* pre = &g_preGates[((size_t)t*B_ + bc)*G4H_];
            const float* p0  = &g_part[0][bc][0];
            const float* p1  = &g_part[1][bc][0];
            const float* p2  = &g_part[2][bc][0];
            const float* p3  = &g_part[3][bc][0];
            float2 gate[4];
            #pragma unroll
            for (int gidx = 0; gidx < 4; gidx++) {
                int o = gidx*512 + u2;
                float2 pv = *(const float2*)&pre[o];
                float2 a = ldcg2(&p0[o]), b = ldcg2(&p1[o]);
                float2 c = ldcg2(&p2[o]), d = ldcg2(&p3[o]);
                gate[gidx].x = pv.x + a.x + b.x + c.x + d.x;
                gate[gidx].y = pv.y + a.y + b.y + c.y + d.y;
            }
            float2 gmv = *(const float2*)&g_gammaH[((size_t)t*B_ + bc)*H_ + u2];
            float tpv = tps[t];
            float c1x = sigm(gate[1].x)*(gmv.x*c_reg.x) + sigm(gate[0].x)*tanhf(gate[2].x);
            float c1y = sigm(gate[1].y)*(gmv.y*c_reg.y) + sigm(gate[0].y)*tanhf(gate[2].y);
            float h1x = sigm(gate[3].x)*tanhf(c1x);
            float h1y = sigm(gate[3].y)*tanhf(c1y);
            float gt0 = sigm(tpv*wtr.x + htr.x);
            float gt1 = sigm(tpv*wtr.y + htr.y);
            c_reg.x = gt0*c1x; c_reg.y = gt1*c1y;
            stcg2(&g_hbuf[p^1][bc][u2], make_float2(gt0*h1x, gt1*h1y));
        }
        gridbar(grp, sense);
    }

    for (int i = tid; i < 512; i += 256)
        h1s[i] = ldcg(&g_hbuf[0][bc][i]);
    __syncthreads();
    {
        int wid = tid >> 5, lane = tid & 31;
        for (int z = wid; z < 10; z += 8) {
            float s = 0.f;
            const float* wv = g_W1T + z*H_;
            #pragma unroll 4
            for (int k = lane; k < H_; k += 32) s = fmaf(h1s[k], __ldg(&wv[k]), s);
            #pragma unroll
            for (int off = 16; off; off >>= 1) s += __shfl_xor_sync(0xffffffffu, s, off);
            if (lane == 0) zs[z] = sigm(s + b1[z]);
        }
        __syncthreads();
        if (tid == 0) {
            float z0 = b2[0], z1 = b2[1];
            #pragma unroll
            for (int j = 0; j < 10; j++) {
                z0 = fmaf(zs[j], W2[j*2 + 0], z0);
                z1 = fmaf(zs[j], W2[j*2 + 1], z1);
            }
            z0 = sigm(z0); z1 = sigm(z1);
            float m = fmaxf(z0, z1);
            float e0 = expf(z0 - m), e1 = expf(z1 - m);
            float inv = 1.f/(e0 + e1);
            out[((size_t)127*B_ + bc)*2 + 0] = e0*inv;
            out[((size_t)127*B_ + bc)*2 + 1] = e1*inv;
        }
    }
}

// ---------------------------------------------------------------------------
extern "C" void kernel_launch(void* const* d_in, const int* in_sizes, int n_in,
                              void* d_out, int out_size)
{
    const float* x     = (const float*)d_in[0];
    const float* dt    = (const float*)d_in[1];
    const float* mask  = (const float*)d_in[2];
    const float* tp    = (const float*)d_in[3];
    const float* xmean = (const float*)d_in[4];
    const float* h0    = (const float*)d_in[5];
    const float* c0    = (const float*)d_in[6];
    const float* wgx   = (const float*)d_in[7];
    const float* hgx   = (const float*)d_in[8];
    const float* wgh   = (const float*)d_in[9];
    const float* hgh   = (const float*)d_in[10];
    const float* wt    = (const float*)d_in[11];
    const float* ht    = (const float*)d_in[12];
    const float* Wih   = (const float*)d_in[13];
    const float* Whh   = (const float*)d_in[14];
    const float* bih   = (const float*)d_in[15];
    const float* bhh   = (const float*)d_in[16];
    const float* W1    = (const float*)d_in[17];
    const float* b1    = (const float*)d_in[18];
    const float* W2    = (const float*)d_in[19];
    const float* b2    = (const float*)d_in[20];
    float* out = (float*)d_out;

    const int LOOP_SMEM = (192*LDK + 512 + 16 + 128) * 4;
    static bool attr_done = false;
    if (!attr_done) {
        cudaFuncSetAttribute(k_g12_h, cudaFuncAttributeMaxDynamicSharedMemorySize, HM_SMEM);
        cudaFuncSetAttribute(k_g3_h,  cudaFuncAttributeMaxDynamicSharedMemorySize, HM_SMEM);
        cudaFuncSetAttribute(k_loop,  cudaFuncAttributeMaxDynamicSharedMemorySize, LOOP_SMEM);
        attr_done = true;
    }

    k_init<<<B_, H_>>>(h0);
    k_tr<<<778, 256>>>(wgx, wgh, W1);
    k_cvt<<<8704, 256>>>(dt, Wih);
    k_g12_h<<<dim3(BT_/128, 6),  256, HM_SMEM>>>(hgx, hgh, x, mask, xmean, out);
    k_g3_h<<<dim3(BT_/128, 16), 256, HM_SMEM>>>(bih, bhh);
    k_loop<<<256, 256, LOOP_SMEM>>>(Whh, c0, tp, wt, ht, b1, W2, b2, out);
}